// round 2
// baseline (speedup 1.0000x reference)
#include <cuda_runtime.h>
#include <cuda_bf16.h>
#include <math.h>

#define L_SEQ 4096
#define D_MODEL 1536
#define N_HEADS 12
#define D_HEAD 128
#define C_HALF 64   // d/2
#define C1 22
#define C2 21

// ---------------- scratch (no allocations allowed) ----------------
__device__ float g_q[L_SEQ * D_MODEL];
__device__ float g_k[L_SEQ * D_MODEL];
__device__ float g_v[L_SEQ * D_MODEL];
__device__ float g_ao[L_SEQ * D_MODEL];

// ---------------- GEMM: C[M,Nn] = A[M,K] * W[Nn,K]^T + bias ----------------
// 64x64 tile, BK=16, 256 threads, 4x4 register tile.
__global__ __launch_bounds__(256) void gemm_nt_bias(
    const float* __restrict__ A, const float* __restrict__ W,
    const float* __restrict__ bias, float* __restrict__ C,
    int M, int Nn, int K) {
  __shared__ float As[16 * 68];
  __shared__ float Bs[16 * 68];
  const int tid = threadIdx.x;
  const int tx = tid & 15, ty = tid >> 4;
  const int m0 = blockIdx.y << 6, n0 = blockIdx.x << 6;
  const int mm = tid >> 2, kk4 = tid & 3;
  const int K4 = K >> 2;
  const float4* A4 = (const float4*)A;
  const float4* W4 = (const float4*)W;

  float acc[4][4];
#pragma unroll
  for (int i = 0; i < 4; i++)
#pragma unroll
    for (int j = 0; j < 4; j++) acc[i][j] = 0.f;

  for (int k0 = 0; k0 < K; k0 += 16) {
    float4 av = A4[(m0 + mm) * K4 + (k0 >> 2) + kk4];
    float4 wv = W4[(n0 + mm) * K4 + (k0 >> 2) + kk4];
    __syncthreads();
    As[(kk4 * 4 + 0) * 68 + mm] = av.x;
    As[(kk4 * 4 + 1) * 68 + mm] = av.y;
    As[(kk4 * 4 + 2) * 68 + mm] = av.z;
    As[(kk4 * 4 + 3) * 68 + mm] = av.w;
    Bs[(kk4 * 4 + 0) * 68 + mm] = wv.x;
    Bs[(kk4 * 4 + 1) * 68 + mm] = wv.y;
    Bs[(kk4 * 4 + 2) * 68 + mm] = wv.z;
    Bs[(kk4 * 4 + 3) * 68 + mm] = wv.w;
    __syncthreads();
#pragma unroll
    for (int kk = 0; kk < 16; kk++) {
      float4 a = *(const float4*)&As[kk * 68 + ty * 4];
      float4 b = *(const float4*)&Bs[kk * 68 + tx * 4];
      float ar[4] = {a.x, a.y, a.z, a.w};
      float br[4] = {b.x, b.y, b.z, b.w};
#pragma unroll
      for (int i = 0; i < 4; i++)
#pragma unroll
        for (int j = 0; j < 4; j++) acc[i][j] += ar[i] * br[j];
    }
  }
  float4 bb = *(const float4*)&bias[n0 + tx * 4];
  float brr[4] = {bb.x, bb.y, bb.z, bb.w};
#pragma unroll
  for (int i = 0; i < 4; i++) {
    int row = m0 + ty * 4 + i;
    float4 o;
    o.x = acc[i][0] + brr[0];
    o.y = acc[i][1] + brr[1];
    o.z = acc[i][2] + brr[2];
    o.w = acc[i][3] + brr[3];
    *(float4*)&C[row * Nn + n0 + tx * 4] = o;
  }
}

// ---------------- fused RMSNorm (* g) + interleaved RoPE ----------------
// one block per token; buf is [L][D] in-place
__global__ __launch_bounds__(256) void rmsnorm_rope(
    float* __restrict__ buf, const float* __restrict__ g,
    const int* __restrict__ grid_sizes,
    const float* __restrict__ fcos, const float* __restrict__ fsin) {
  const int t = blockIdx.x;
  const int tid = threadIdx.x;
  float* row = buf + (size_t)t * D_MODEL;

  float ss = 0.f;
  for (int i = tid; i < D_MODEL; i += 256) {
    float xv = row[i];
    ss += xv * xv;
  }
#pragma unroll
  for (int o = 16; o; o >>= 1) ss += __shfl_xor_sync(0xffffffffu, ss, o);
  __shared__ float red[8];
  if ((tid & 31) == 0) red[tid >> 5] = ss;

  const int f = grid_sizes[0], h = grid_sizes[1], w = grid_sizes[2];
  const int sl = f * h * w;

  __shared__ float cs[C_HALF], sn[C_HALF];
  if (t < sl && tid < C_HALF) {
    int fi = t / (h * w);
    int rem = t - fi * h * w;
    int hi = rem / w;
    int wi = rem - hi * w;
    int jj = tid;
    int rowp = (jj < C1) ? fi : ((jj < C1 + C2) ? hi : wi);
    cs[jj] = fcos[rowp * C_HALF + jj];
    sn[jj] = fsin[rowp * C_HALF + jj];
  }
  __syncthreads();
  float tot = red[0] + red[1] + red[2] + red[3] + red[4] + red[5] + red[6] + red[7];
  float rinv = rsqrtf(tot * (1.0f / D_MODEL) + 1e-6f);

  if (t < sl) {
    for (int p = tid; p < N_HEADS * C_HALF; p += 256) {
      int head = p >> 6;
      int jj = p & 63;
      int i0 = head * D_HEAD + 2 * jj;
      float y0 = row[i0] * rinv * g[i0];
      float y1 = row[i0 + 1] * rinv * g[i0 + 1];
      float cv = cs[jj], sv = sn[jj];
      row[i0] = y0 * cv - y1 * sv;
      row[i0 + 1] = y0 * sv + y1 * cv;
    }
  } else {
    for (int i = tid; i < D_MODEL; i += 256) row[i] = row[i] * rinv * g[i];
  }
}

// ---------------- flash attention ----------------
// grid (L/64, N_HEADS), 256 threads. Q tile 64, KV tile 64, d=128, fp32.
#define QS_STRIDE 132
#define SS_STRIDE 65
#define ATTN_SMEM ((64 * QS_STRIDE * 2 + 64 * SS_STRIDE) * 4)

__global__ __launch_bounds__(256, 2) void attn_kernel(
    const float* __restrict__ q, const float* __restrict__ k,
    const float* __restrict__ v, const int* __restrict__ seq_lens,
    float* __restrict__ o) {
  extern __shared__ float smem[];
  float* Qs = smem;                       // [64][132]
  float* KV = smem + 64 * QS_STRIDE;      // [64][132] (K then V)
  float* Ss = smem + 2 * 64 * QS_STRIDE;  // [64][65]

  const int tid = threadIdx.x;
  const int q0 = blockIdx.x << 6;
  const int head = blockIdx.y;
  const int seqlen = seq_lens[0];
  const int tx = tid & 15, ty = tid >> 4;
  const int r_own = tid >> 2, cg = tid & 3;

  const float4* q4 = (const float4*)q;
  const float4* k4 = (const float4*)k;
  const float4* v4g = (const float4*)v;
  const int rowstride4 = D_MODEL / 4;  // 384
  const int hoff4 = head * (D_HEAD / 4);  // head*32

  // load Q tile (pre-scaled by 1/sqrt(d))
  const float sc = 0.08838834764831845f;
  for (int m = tid; m < 64 * 32; m += 256) {
    int r = m >> 5, c4 = m & 31;
    float4 tq = q4[(q0 + r) * rowstride4 + hoff4 + c4];
    tq.x *= sc; tq.y *= sc; tq.z *= sc; tq.w *= sc;
    *(float4*)&Qs[r * QS_STRIDE + c4 * 4] = tq;
  }

  float m_i = -INFINITY, l_i = 0.f;
  float acc[32];
#pragma unroll
  for (int j = 0; j < 32; j++) acc[j] = 0.f;

  for (int kt = 0; kt < 64; kt++) {
    __syncthreads();  // prev PV done (KV, Ss free); Qs ready on first iter
    for (int m = tid; m < 64 * 32; m += 256) {
      int r = m >> 5, c4 = m & 31;
      *(float4*)&KV[r * QS_STRIDE + c4 * 4] =
          k4[(kt * 64 + r) * rowstride4 + hoff4 + c4];
    }
    __syncthreads();

    // S = Q K^T (64x64), thread -> rows ty+16i, cols tx+16j
    float s4[4][4];
#pragma unroll
    for (int i = 0; i < 4; i++)
#pragma unroll
      for (int j = 0; j < 4; j++) s4[i][j] = 0.f;

#pragma unroll 4
    for (int kk4 = 0; kk4 < 32; kk4++) {
      float4 a[4], b[4];
#pragma unroll
      for (int i = 0; i < 4; i++)
        a[i] = *(const float4*)&Qs[(ty + 16 * i) * QS_STRIDE + kk4 * 4];
#pragma unroll
      for (int j = 0; j < 4; j++)
        b[j] = *(const float4*)&KV[(tx + 16 * j) * QS_STRIDE + kk4 * 4];
#pragma unroll
      for (int i = 0; i < 4; i++)
#pragma unroll
        for (int j = 0; j < 4; j++)
          s4[i][j] += a[i].x * b[j].x + a[i].y * b[j].y +
                      a[i].z * b[j].z + a[i].w * b[j].w;
    }
#pragma unroll
    for (int i = 0; i < 4; i++)
#pragma unroll
      for (int j = 0; j < 4; j++)
        Ss[(ty + 16 * i) * SS_STRIDE + tx + 16 * j] = s4[i][j];
    __syncthreads();  // S complete; KV reads complete

    // load V tile into KV (overwrites K)
    for (int m = tid; m < 64 * 32; m += 256) {
      int r = m >> 5, c4 = m & 31;
      *(float4*)&KV[r * QS_STRIDE + c4 * 4] =
          v4g[(kt * 64 + r) * rowstride4 + hoff4 + c4];
    }

    // online softmax: thread owns row r_own, cols cg*16..cg*16+15
    float sv[16];
    float mx = -INFINITY;
#pragma unroll
    for (int u = 0; u < 16; u++) {
      int c = cg * 16 + u;
      float s = Ss[r_own * SS_STRIDE + c];
      if (kt * 64 + c >= seqlen) s = -1e30f;
      sv[u] = s;
      mx = fmaxf(mx, s);
    }
    mx = fmaxf(mx, __shfl_xor_sync(0xffffffffu, mx, 1));
    mx = fmaxf(mx, __shfl_xor_sync(0xffffffffu, mx, 2));
    float m_new = fmaxf(m_i, mx);
    float corr = __expf(m_i - m_new);
    float ssum = 0.f;
#pragma unroll
    for (int u = 0; u < 16; u++) {
      float p = __expf(sv[u] - m_new);
      Ss[r_own * SS_STRIDE + cg * 16 + u] = p;
      ssum += p;
    }
    ssum += __shfl_xor_sync(0xffffffffu, ssum, 1);
    ssum += __shfl_xor_sync(0xffffffffu, ssum, 2);
    l_i = l_i * corr + ssum;
    m_i = m_new;
#pragma unroll
    for (int j = 0; j < 32; j++) acc[j] *= corr;
    __syncthreads();  // V + P complete

    // O += P * V ; thread owns (row r_own, dims cg*32..cg*32+31)
#pragma unroll 4
    for (int c = 0; c < 64; c++) {
      float p = Ss[r_own * SS_STRIDE + c];
      const float* vr = &KV[c * QS_STRIDE + cg * 32];
#pragma unroll
      for (int j4 = 0; j4 < 8; j4++) {
        float4 vv = *(const float4*)&vr[j4 * 4];
        acc[j4 * 4 + 0] += p * vv.x;
        acc[j4 * 4 + 1] += p * vv.y;
        acc[j4 * 4 + 2] += p * vv.z;
        acc[j4 * 4 + 3] += p * vv.w;
      }
    }
  }

  float inv = 1.f / l_i;
  float4* o4 = (float4*)o;
#pragma unroll
  for (int j4 = 0; j4 < 8; j4++) {
    float4 t;
    t.x = acc[j4 * 4 + 0] * inv;
    t.y = acc[j4 * 4 + 1] * inv;
    t.z = acc[j4 * 4 + 2] * inv;
    t.w = acc[j4 * 4 + 3] * inv;
    o4[(q0 + r_own) * rowstride4 + hoff4 + cg * 8 + j4] = t;
  }
}

// ---------------- launch ----------------
extern "C" void kernel_launch(void* const* d_in, const int* in_sizes, int n_in,
                              void* d_out, int out_size) {
  const float* x = (const float*)d_in[0];
  const int* seq_lens = (const int*)d_in[1];
  const int* grid_sizes = (const int*)d_in[2];
  const float* fcos = (const float*)d_in[3];
  const float* fsin = (const float*)d_in[4];
  const float* Wq = (const float*)d_in[5];
  const float* bq = (const float*)d_in[6];
  const float* Wk = (const float*)d_in[7];
  const float* bk = (const float*)d_in[8];
  const float* Wv = (const float*)d_in[9];
  const float* bv = (const float*)d_in[10];
  const float* Wo = (const float*)d_in[11];
  const float* bo = (const float*)d_in[12];
  const float* gq = (const float*)d_in[13];
  const float* gk = (const float*)d_in[14];
  float* out = (float*)d_out;

  void *pq, *pk, *pv, *pao;
  cudaGetSymbolAddress(&pq, g_q);
  cudaGetSymbolAddress(&pk, g_k);
  cudaGetSymbolAddress(&pv, g_v);
  cudaGetSymbolAddress(&pao, g_ao);
  float* fq = (float*)pq;
  float* fk = (float*)pk;
  float* fv = (float*)pv;
  float* fao = (float*)pao;

  dim3 gg(D_MODEL / 64, L_SEQ / 64);
  gemm_nt_bias<<<gg, 256>>>(x, Wq, bq, fq, L_SEQ, D_MODEL, D_MODEL);
  gemm_nt_bias<<<gg, 256>>>(x, Wk, bk, fk, L_SEQ, D_MODEL, D_MODEL);
  gemm_nt_bias<<<gg, 256>>>(x, Wv, bv, fv, L_SEQ, D_MODEL, D_MODEL);

  rmsnorm_rope<<<L_SEQ, 256>>>(fq, gq, grid_sizes, fcos, fsin);
  rmsnorm_rope<<<L_SEQ, 256>>>(fk, gk, grid_sizes, fcos, fsin);

  cudaFuncSetAttribute(attn_kernel, cudaFuncAttributeMaxDynamicSharedMemorySize,
                       ATTN_SMEM);
  attn_kernel<<<dim3(L_SEQ / 64, N_HEADS), 256, ATTN_SMEM>>>(fq, fk, fv,
                                                             seq_lens, fao);

  gemm_nt_bias<<<gg, 256>>>(fao, Wo, bo, out, L_SEQ, D_MODEL, D_MODEL);
}

// round 3
// speedup vs baseline: 8.9096x; 8.9096x over previous
#include <cuda_runtime.h>
#include <math.h>

#define L_SEQ 4096
#define D_MODEL 1536
#define N_HEADS 12
#define D_HEAD 128
#define C_HALF 64   // d/2
#define C1 22
#define C2 21

// ---------------- scratch (no allocations allowed) ----------------
__device__ float g_q[L_SEQ * D_MODEL];
__device__ float g_k[L_SEQ * D_MODEL];
__device__ float g_v[L_SEQ * D_MODEL];
__device__ float g_ao[L_SEQ * D_MODEL];

// ---------------- helpers ----------------
__device__ __forceinline__ unsigned f2tf(float f) {
  unsigned u;
  asm("cvt.rna.tf32.f32 %0, %1;" : "=r"(u) : "f"(f));
  return u;
}

__device__ __forceinline__ void mma8(float* c, const unsigned* a,
                                     const unsigned* b) {
  asm volatile(
      "mma.sync.aligned.m16n8k8.row.col.f32.tf32.tf32.f32 "
      "{%0,%1,%2,%3},{%4,%5,%6,%7},{%8,%9},{%0,%1,%2,%3};\n"
      : "+f"(c[0]), "+f"(c[1]), "+f"(c[2]), "+f"(c[3])
      : "r"(a[0]), "r"(a[1]), "r"(a[2]), "r"(a[3]), "r"(b[0]), "r"(b[1]));
}

// ---------------- TF32 GEMM: C[M,Nn] = A[M,K] * W[Nn,K]^T + bias -------------
// 128x128 tile, BK=32, 256 threads (8 warps, 2m x 4n), warp tile 64x32.
__global__ __launch_bounds__(256) void gemm_tf32(
    const float* __restrict__ A, const float* __restrict__ W,
    const float* __restrict__ bias, float* __restrict__ C,
    int M, int Nn, int K) {
  __shared__ unsigned As[128 * 36];
  __shared__ unsigned Bs[128 * 36];
  const int tid = threadIdx.x, lane = tid & 31, warp = tid >> 5;
  const int wm = warp >> 2, wn = warp & 3;
  const int m0 = blockIdx.y << 7, n0 = blockIdx.x << 7;
  const int K4 = K >> 2;
  const float4* A4 = (const float4*)A;
  const float4* W4 = (const float4*)W;
  const int lr = tid >> 3, lc = tid & 7;

  float acc[4][4][4];
#pragma unroll
  for (int mf = 0; mf < 4; mf++)
#pragma unroll
    for (int nf = 0; nf < 4; nf++)
#pragma unroll
      for (int u = 0; u < 4; u++) acc[mf][nf][u] = 0.f;

  for (int k0 = 0; k0 < K; k0 += 32) {
    float4 ar[4], wr[4];
#pragma unroll
    for (int i = 0; i < 4; i++) {
      ar[i] = A4[(size_t)(m0 + lr + 32 * i) * K4 + (k0 >> 2) + lc];
      wr[i] = W4[(size_t)(n0 + lr + 32 * i) * K4 + (k0 >> 2) + lc];
    }
    __syncthreads();
#pragma unroll
    for (int i = 0; i < 4; i++) {
      int base = (lr + 32 * i) * 36 + lc * 4;
      As[base + 0] = f2tf(ar[i].x);
      As[base + 1] = f2tf(ar[i].y);
      As[base + 2] = f2tf(ar[i].z);
      As[base + 3] = f2tf(ar[i].w);
      Bs[base + 0] = f2tf(wr[i].x);
      Bs[base + 1] = f2tf(wr[i].y);
      Bs[base + 2] = f2tf(wr[i].z);
      Bs[base + 3] = f2tf(wr[i].w);
    }
    __syncthreads();
#pragma unroll
    for (int s = 0; s < 4; s++) {
      const int kk = (s << 3) + (lane & 3);
      unsigned a[4][4], b[4][2];
#pragma unroll
      for (int mf = 0; mf < 4; mf++) {
        int r = (wm << 6) + (mf << 4) + (lane >> 2);
        a[mf][0] = As[r * 36 + kk];
        a[mf][1] = As[(r + 8) * 36 + kk];
        a[mf][2] = As[r * 36 + kk + 4];
        a[mf][3] = As[(r + 8) * 36 + kk + 4];
      }
#pragma unroll
      for (int nf = 0; nf < 4; nf++) {
        int n = (wn << 5) + (nf << 3) + (lane >> 2);
        b[nf][0] = Bs[n * 36 + kk];
        b[nf][1] = Bs[n * 36 + kk + 4];
      }
#pragma unroll
      for (int mf = 0; mf < 4; mf++)
#pragma unroll
        for (int nf = 0; nf < 4; nf++) mma8(acc[mf][nf], a[mf], b[nf]);
    }
  }
#pragma unroll
  for (int mf = 0; mf < 4; mf++) {
    int r = m0 + (wm << 6) + (mf << 4) + (lane >> 2);
#pragma unroll
    for (int nf = 0; nf < 4; nf++) {
      int c = n0 + (wn << 5) + (nf << 3) + ((lane & 3) << 1);
      float b0 = bias[c], b1 = bias[c + 1];
      float2 o0 = {acc[mf][nf][0] + b0, acc[mf][nf][1] + b1};
      *(float2*)&C[(size_t)r * Nn + c] = o0;
      float2 o1 = {acc[mf][nf][2] + b0, acc[mf][nf][3] + b1};
      *(float2*)&C[(size_t)(r + 8) * Nn + c] = o1;
    }
  }
}

// ---------------- fused RMSNorm (* g) + interleaved RoPE ----------------
__global__ __launch_bounds__(256) void rmsnorm_rope(
    float* __restrict__ buf, const float* __restrict__ g,
    const int* __restrict__ grid_sizes,
    const float* __restrict__ fcos, const float* __restrict__ fsin) {
  const int t = blockIdx.x;
  const int tid = threadIdx.x;
  float* row = buf + (size_t)t * D_MODEL;

  float ss = 0.f;
  for (int i = tid; i < D_MODEL; i += 256) {
    float xv = row[i];
    ss += xv * xv;
  }
#pragma unroll
  for (int o = 16; o; o >>= 1) ss += __shfl_xor_sync(0xffffffffu, ss, o);
  __shared__ float red[8];
  if ((tid & 31) == 0) red[tid >> 5] = ss;

  const int f = grid_sizes[0], h = grid_sizes[1], w = grid_sizes[2];
  const int sl = f * h * w;

  __shared__ float cs[C_HALF], sn[C_HALF];
  if (t < sl && tid < C_HALF) {
    int fi = t / (h * w);
    int rem = t - fi * h * w;
    int hi = rem / w;
    int wi = rem - hi * w;
    int jj = tid;
    int rowp = (jj < C1) ? fi : ((jj < C1 + C2) ? hi : wi);
    cs[jj] = fcos[rowp * C_HALF + jj];
    sn[jj] = fsin[rowp * C_HALF + jj];
  }
  __syncthreads();
  float tot = red[0] + red[1] + red[2] + red[3] + red[4] + red[5] + red[6] + red[7];
  float rinv = rsqrtf(tot * (1.0f / D_MODEL) + 1e-6f);

  if (t < sl) {
    for (int p = tid; p < N_HEADS * C_HALF; p += 256) {
      int head = p >> 6;
      int jj = p & 63;
      int i0 = head * D_HEAD + 2 * jj;
      float y0 = row[i0] * rinv * g[i0];
      float y1 = row[i0 + 1] * rinv * g[i0 + 1];
      float cv = cs[jj], sv = sn[jj];
      row[i0] = y0 * cv - y1 * sv;
      row[i0 + 1] = y0 * sv + y1 * cv;
    }
  } else {
    for (int i = tid; i < D_MODEL; i += 256) row[i] = row[i] * rinv * g[i];
  }
}

// ---------------- TF32 flash attention ----------------
// grid (L/128, N_HEADS), 256 threads (8 warps). Q tile 128, KV tile 64.
// Warp w owns S/O rows 16w..16w+15. Softmax fully in registers.
#define QS_STR 132
#define PS_STR 68
#define ATTN_SMEM (((128 + 64 + 64) * QS_STR + 128 * PS_STR) * 4)

__global__ __launch_bounds__(256) void attn_tf32(
    const float* __restrict__ q, const float* __restrict__ k,
    const float* __restrict__ v, const int* __restrict__ seq_lens,
    float* __restrict__ o) {
  extern __shared__ unsigned sm[];
  unsigned* Qs = sm;                  // [128][132]
  unsigned* Ks = Qs + 128 * QS_STR;   // [64][132]
  unsigned* Vs = Ks + 64 * QS_STR;    // [64][132]
  unsigned* Ps = Vs + 64 * QS_STR;    // [128][68]

  const int tid = threadIdx.x, lane = tid & 31, warp = tid >> 5;
  const int q0 = blockIdx.x << 7, head = blockIdx.y;
  const int seqlen = seq_lens[0];
  const float4* q4 = (const float4*)q;
  const float4* k4 = (const float4*)k;
  const float4* v4 = (const float4*)v;
  const int rs4 = D_MODEL / 4;        // 384
  const int h4 = head * (D_HEAD / 4); // head*32
  const float scq = 0.08838834764831845f;  // 1/sqrt(128)
  const int rq = (lane >> 2);
  const int r_own = (warp << 4) + rq;      // this thread's row (and +8)

  // load + scale + cvt Q tile
#pragma unroll
  for (int i = 0; i < 16; i++) {
    int idx = tid + (i << 8);
    int r = idx >> 5, c4 = idx & 31;
    float4 t = q4[(size_t)(q0 + r) * rs4 + h4 + c4];
    uint4 u = {f2tf(t.x * scq), f2tf(t.y * scq), f2tf(t.z * scq),
               f2tf(t.w * scq)};
    *(uint4*)&Qs[r * QS_STR + (c4 << 2)] = u;
  }

  float m0r = -INFINITY, m1r = -INFINITY, l0 = 0.f, l1 = 0.f;
  float oac[16][4];
#pragma unroll
  for (int j = 0; j < 16; j++)
#pragma unroll
    for (int u = 0; u < 4; u++) oac[j][u] = 0.f;

  for (int kt = 0; kt < 64; kt++) {
    __syncthreads();  // prev PV done: Ks/Vs free (and Qs ready on iter 0)
#pragma unroll
    for (int i = 0; i < 8; i++) {
      int idx = tid + (i << 8);
      int r = idx >> 5, c4 = idx & 31;
      float4 tk = k4[(size_t)((kt << 6) + r) * rs4 + h4 + c4];
      uint4 uk = {f2tf(tk.x), f2tf(tk.y), f2tf(tk.z), f2tf(tk.w)};
      *(uint4*)&Ks[r * QS_STR + (c4 << 2)] = uk;
      float4 tv = v4[(size_t)((kt << 6) + r) * rs4 + h4 + c4];
      uint4 uv = {f2tf(tv.x), f2tf(tv.y), f2tf(tv.z), f2tf(tv.w)};
      *(uint4*)&Vs[r * QS_STR + (c4 << 2)] = uv;
    }
    __syncthreads();

    // S = Q K^T : warp rows 16w..16w+15, all 64 cols, k=128
    float sacc[8][4];
#pragma unroll
    for (int j = 0; j < 8; j++)
#pragma unroll
      for (int u = 0; u < 4; u++) sacc[j][u] = 0.f;

#pragma unroll
    for (int s = 0; s < 16; s++) {
      int kk = (s << 3) + (lane & 3);
      unsigned a[4];
      a[0] = Qs[r_own * QS_STR + kk];
      a[1] = Qs[(r_own + 8) * QS_STR + kk];
      a[2] = Qs[r_own * QS_STR + kk + 4];
      a[3] = Qs[(r_own + 8) * QS_STR + kk + 4];
#pragma unroll
      for (int j = 0; j < 8; j++) {
        int n = (j << 3) + rq;
        unsigned b[2] = {Ks[n * QS_STR + kk], Ks[n * QS_STR + kk + 4]};
        mma8(sacc[j], a, b);
      }
    }

    // mask (only triggers on the ragged tail)
    if (((kt << 6) + 63) >= seqlen) {
#pragma unroll
      for (int j = 0; j < 8; j++) {
        int c = (kt << 6) + (j << 3) + ((lane & 3) << 1);
        if (c >= seqlen) { sacc[j][0] = -1e30f; sacc[j][2] = -1e30f; }
        if (c + 1 >= seqlen) { sacc[j][1] = -1e30f; sacc[j][3] = -1e30f; }
      }
    }

    // register softmax: rows r_own (c0,c1) and r_own+8 (c2,c3)
    float mx0 = -INFINITY, mx1 = -INFINITY;
#pragma unroll
    for (int j = 0; j < 8; j++) {
      mx0 = fmaxf(mx0, fmaxf(sacc[j][0], sacc[j][1]));
      mx1 = fmaxf(mx1, fmaxf(sacc[j][2], sacc[j][3]));
    }
    mx0 = fmaxf(mx0, __shfl_xor_sync(0xffffffffu, mx0, 1));
    mx0 = fmaxf(mx0, __shfl_xor_sync(0xffffffffu, mx0, 2));
    mx1 = fmaxf(mx1, __shfl_xor_sync(0xffffffffu, mx1, 1));
    mx1 = fmaxf(mx1, __shfl_xor_sync(0xffffffffu, mx1, 2));
    float mn0 = fmaxf(m0r, mx0), mn1 = fmaxf(m1r, mx1);
    float co0 = __expf(m0r - mn0), co1 = __expf(m1r - mn1);
    float s0 = 0.f, s1 = 0.f;
#pragma unroll
    for (int j = 0; j < 8; j++) {
      float p0 = __expf(sacc[j][0] - mn0);
      float p1 = __expf(sacc[j][1] - mn0);
      float p2 = __expf(sacc[j][2] - mn1);
      float p3 = __expf(sacc[j][3] - mn1);
      s0 += p0 + p1;
      s1 += p2 + p3;
      int c = (j << 3) + ((lane & 3) << 1);
      uint2 w0 = {f2tf(p0), f2tf(p1)};
      *(uint2*)&Ps[r_own * PS_STR + c] = w0;
      uint2 w1 = {f2tf(p2), f2tf(p3)};
      *(uint2*)&Ps[(r_own + 8) * PS_STR + c] = w1;
    }
    s0 += __shfl_xor_sync(0xffffffffu, s0, 1);
    s0 += __shfl_xor_sync(0xffffffffu, s0, 2);
    s1 += __shfl_xor_sync(0xffffffffu, s1, 1);
    s1 += __shfl_xor_sync(0xffffffffu, s1, 2);
    l0 = l0 * co0 + s0;
    l1 = l1 * co1 + s1;
    m0r = mn0;
    m1r = mn1;
#pragma unroll
    for (int j = 0; j < 16; j++) {
      oac[j][0] *= co0;
      oac[j][1] *= co0;
      oac[j][2] *= co1;
      oac[j][3] *= co1;
    }
    __syncwarp();  // Ps rows are per-warp private; warp-level visibility only

    // O += P V : warp rows 16w.., n=128, k=64
#pragma unroll
    for (int s = 0; s < 8; s++) {
      int kk = (s << 3) + (lane & 3);
      unsigned a[4];
      a[0] = Ps[r_own * PS_STR + kk];
      a[1] = Ps[(r_own + 8) * PS_STR + kk];
      a[2] = Ps[r_own * PS_STR + kk + 4];
      a[3] = Ps[(r_own + 8) * PS_STR + kk + 4];
#pragma unroll
      for (int j = 0; j < 16; j++) {
        int n = (j << 3) + rq;
        unsigned b[2] = {Vs[kk * QS_STR + n], Vs[(kk + 4) * QS_STR + n]};
        mma8(oac[j], a, b);
      }
    }
  }

  float i0 = 1.f / l0, i1 = 1.f / l1;
#pragma unroll
  for (int j = 0; j < 16; j++) {
    int c = (j << 3) + ((lane & 3) << 1);
    float2 a = {oac[j][0] * i0, oac[j][1] * i0};
    *(float2*)&o[(size_t)(q0 + r_own) * D_MODEL + head * D_HEAD + c] = a;
    float2 b = {oac[j][2] * i1, oac[j][3] * i1};
    *(float2*)&o[(size_t)(q0 + r_own + 8) * D_MODEL + head * D_HEAD + c] = b;
  }
}

// ---------------- launch ----------------
extern "C" void kernel_launch(void* const* d_in, const int* in_sizes, int n_in,
                              void* d_out, int out_size) {
  const float* x = (const float*)d_in[0];
  const int* seq_lens = (const int*)d_in[1];
  const int* grid_sizes = (const int*)d_in[2];
  const float* fcos = (const float*)d_in[3];
  const float* fsin = (const float*)d_in[4];
  const float* Wq = (const float*)d_in[5];
  const float* bq = (const float*)d_in[6];
  const float* Wk = (const float*)d_in[7];
  const float* bk = (const float*)d_in[8];
  const float* Wv = (const float*)d_in[9];
  const float* bv = (const float*)d_in[10];
  const float* Wo = (const float*)d_in[11];
  const float* bo = (const float*)d_in[12];
  const float* gq = (const float*)d_in[13];
  const float* gk = (const float*)d_in[14];
  float* out = (float*)d_out;

  void *pq, *pk, *pv, *pao;
  cudaGetSymbolAddress(&pq, g_q);
  cudaGetSymbolAddress(&pk, g_k);
  cudaGetSymbolAddress(&pv, g_v);
  cudaGetSymbolAddress(&pao, g_ao);
  float* fq = (float*)pq;
  float* fk = (float*)pk;
  float* fv = (float*)pv;
  float* fao = (float*)pao;

  dim3 gg(D_MODEL / 128, L_SEQ / 128);
  gemm_tf32<<<gg, 256>>>(x, Wq, bq, fq, L_SEQ, D_MODEL, D_MODEL);
  gemm_tf32<<<gg, 256>>>(x, Wk, bk, fk, L_SEQ, D_MODEL, D_MODEL);
  gemm_tf32<<<gg, 256>>>(x, Wv, bv, fv, L_SEQ, D_MODEL, D_MODEL);

  rmsnorm_rope<<<L_SEQ, 256>>>(fq, gq, grid_sizes, fcos, fsin);
  rmsnorm_rope<<<L_SEQ, 256>>>(fk, gk, grid_sizes, fcos, fsin);

  cudaFuncSetAttribute(attn_tf32, cudaFuncAttributeMaxDynamicSharedMemorySize,
                       ATTN_SMEM);
  attn_tf32<<<dim3(L_SEQ / 128, N_HEADS), 256, ATTN_SMEM>>>(fq, fk, fv,
                                                            seq_lens, fao);

  gemm_tf32<<<gg, 256>>>(fao, Wo, bo, out, L_SEQ, D_MODEL, D_MODEL);
}

// round 6
// speedup vs baseline: 10.3672x; 1.1636x over previous
#include <cuda_runtime.h>
#include <math.h>

#define L_SEQ 4096
#define D_MODEL 1536
#define N_HEADS 12
#define D_HEAD 128
#define C_HALF 64   // d/2
#define ROPE_C1 22
#define ROPE_C2 21

// ---------------- scratch (no allocations allowed) ----------------
__device__ float g_q[L_SEQ * D_MODEL];
__device__ float g_k[L_SEQ * D_MODEL];
__device__ float g_v[L_SEQ * D_MODEL];
__device__ float g_ao[L_SEQ * D_MODEL];

// ---------------- helpers ----------------
__device__ __forceinline__ unsigned f2tf(float f) {
  unsigned u;
  asm("cvt.rna.tf32.f32 %0, %1;" : "=r"(u) : "f"(f));
  return u;
}

__device__ __forceinline__ void mma8(float* c, const unsigned* a,
                                     const unsigned* b) {
  asm volatile(
      "mma.sync.aligned.m16n8k8.row.col.f32.tf32.tf32.f32 "
      "{%0,%1,%2,%3},{%4,%5,%6,%7},{%8,%9},{%0,%1,%2,%3};\n"
      : "+f"(c[0]), "+f"(c[1]), "+f"(c[2]), "+f"(c[3])
      : "r"(a[0]), "r"(a[1]), "r"(a[2]), "r"(a[3]), "r"(b[0]), "r"(b[1]));
}

// ---------------- TF32 GEMM: C[M,Nn] = A[M,K] * W[Nn,K]^T + bias -------------
// 128x128 tile, BK=32, 256 threads (8 warps, 2m x 4n), warp tile 64x32.
// gridDim.z selects (W,bias,C) triple -> merged QKV in one launch.
// Register-prefetch software pipeline hides L2 latency behind MMA compute.
__global__ __launch_bounds__(256) void gemm_tf32(
    const float* __restrict__ Amat,
    const float* __restrict__ Wz0, const float* __restrict__ Wz1,
    const float* __restrict__ Wz2,
    const float* __restrict__ bz0, const float* __restrict__ bz1,
    const float* __restrict__ bz2,
    float* __restrict__ Cz0, float* __restrict__ Cz1, float* __restrict__ Cz2,
    int Mdim, int Ndim, int Kdim) {
  const int zi = blockIdx.z;
  const float* Wmat = (zi == 0) ? Wz0 : (zi == 1) ? Wz1 : Wz2;
  const float* bias = (zi == 0) ? bz0 : (zi == 1) ? bz1 : bz2;
  float* Cmat = (zi == 0) ? Cz0 : (zi == 1) ? Cz1 : Cz2;

  __shared__ unsigned As[128 * 36];
  __shared__ unsigned Bs[128 * 36];
  const int tid = threadIdx.x, lane = tid & 31, warp = tid >> 5;
  const int wm = warp >> 2, wn = warp & 3;
  const int m0 = blockIdx.y << 7, n0 = blockIdx.x << 7;
  const int K4 = Kdim >> 2;
  const float4* A4 = (const float4*)Amat;
  const float4* W4 = (const float4*)Wmat;
  const int lr = tid >> 3, lc = tid & 7;

  float acc[4][4][4];
#pragma unroll
  for (int mf = 0; mf < 4; mf++)
#pragma unroll
    for (int nf = 0; nf < 4; nf++)
#pragma unroll
      for (int u = 0; u < 4; u++) acc[mf][nf][u] = 0.f;

  float4 ar[4], wr[4];
#pragma unroll
  for (int i = 0; i < 4; i++) {
    ar[i] = A4[(size_t)(m0 + lr + 32 * i) * K4 + lc];
    wr[i] = W4[(size_t)(n0 + lr + 32 * i) * K4 + lc];
  }

  for (int k0 = 0; k0 < Kdim; k0 += 32) {
    __syncthreads();  // previous compute done; smem free
#pragma unroll
    for (int i = 0; i < 4; i++) {
      int base = (lr + 32 * i) * 36 + lc * 4;
      As[base + 0] = f2tf(ar[i].x);
      As[base + 1] = f2tf(ar[i].y);
      As[base + 2] = f2tf(ar[i].z);
      As[base + 3] = f2tf(ar[i].w);
      Bs[base + 0] = f2tf(wr[i].x);
      Bs[base + 1] = f2tf(wr[i].y);
      Bs[base + 2] = f2tf(wr[i].z);
      Bs[base + 3] = f2tf(wr[i].w);
    }
    __syncthreads();
    // prefetch next K-tile; latency hidden by the MMA section below
    const int kn = (k0 + 32 < Kdim) ? (k0 + 32) : k0;
#pragma unroll
    for (int i = 0; i < 4; i++) {
      ar[i] = A4[(size_t)(m0 + lr + 32 * i) * K4 + (kn >> 2) + lc];
      wr[i] = W4[(size_t)(n0 + lr + 32 * i) * K4 + (kn >> 2) + lc];
    }
#pragma unroll
    for (int s = 0; s < 4; s++) {
      const int kk = (s << 3) + (lane & 3);
      unsigned a[4][4], b[4][2];
#pragma unroll
      for (int mf = 0; mf < 4; mf++) {
        int r = (wm << 6) + (mf << 4) + (lane >> 2);
        a[mf][0] = As[r * 36 + kk];
        a[mf][1] = As[(r + 8) * 36 + kk];
        a[mf][2] = As[r * 36 + kk + 4];
        a[mf][3] = As[(r + 8) * 36 + kk + 4];
      }
#pragma unroll
      for (int nf = 0; nf < 4; nf++) {
        int n = (wn << 5) + (nf << 3) + (lane >> 2);
        b[nf][0] = Bs[n * 36 + kk];
        b[nf][1] = Bs[n * 36 + kk + 4];
      }
#pragma unroll
      for (int mf = 0; mf < 4; mf++)
#pragma unroll
        for (int nf = 0; nf < 4; nf++) mma8(acc[mf][nf], a[mf], b[nf]);
    }
  }
#pragma unroll
  for (int mf = 0; mf < 4; mf++) {
    int r = m0 + (wm << 6) + (mf << 4) + (lane >> 2);
#pragma unroll
    for (int nf = 0; nf < 4; nf++) {
      int c = n0 + (wn << 5) + (nf << 3) + ((lane & 3) << 1);
      float bb0 = bias[c], bb1 = bias[c + 1];
      float2 o0 = {acc[mf][nf][0] + bb0, acc[mf][nf][1] + bb1};
      *(float2*)&Cmat[(size_t)r * Ndim + c] = o0;
      float2 o1 = {acc[mf][nf][2] + bb0, acc[mf][nf][3] + bb1};
      *(float2*)&Cmat[(size_t)(r + 8) * Ndim + c] = o1;
    }
  }
}

// ---------------- fused RMSNorm (* g) + interleaved RoPE ----------------
// grid (L, 2): y=0 -> q buffer with gq, y=1 -> k buffer with gk
__global__ __launch_bounds__(256) void rmsnorm_rope(
    float* __restrict__ bufq, float* __restrict__ bufk,
    const float* __restrict__ gqp, const float* __restrict__ gkp,
    const int* __restrict__ grid_sizes,
    const float* __restrict__ fcos, const float* __restrict__ fsin) {
  const int t = blockIdx.x;
  const int tid = threadIdx.x;
  float* row = ((blockIdx.y == 0) ? bufq : bufk) + (size_t)t * D_MODEL;
  const float* g = (blockIdx.y == 0) ? gqp : gkp;

  float ss = 0.f;
  for (int i = tid; i < D_MODEL; i += 256) {
    float xv = row[i];
    ss += xv * xv;
  }
#pragma unroll
  for (int o = 16; o; o >>= 1) ss += __shfl_xor_sync(0xffffffffu, ss, o);
  __shared__ float red[8];
  if ((tid & 31) == 0) red[tid >> 5] = ss;

  const int f = grid_sizes[0], h = grid_sizes[1], w = grid_sizes[2];
  const int sl = f * h * w;

  __shared__ float cs[C_HALF], sn[C_HALF];
  if (t < sl && tid < C_HALF) {
    int fi = t / (h * w);
    int rem = t - fi * h * w;
    int hi = rem / w;
    int wi = rem - hi * w;
    int jj = tid;
    int rowp = (jj < ROPE_C1) ? fi : ((jj < ROPE_C1 + ROPE_C2) ? hi : wi);
    cs[jj] = fcos[rowp * C_HALF + jj];
    sn[jj] = fsin[rowp * C_HALF + jj];
  }
  __syncthreads();
  float tot = red[0] + red[1] + red[2] + red[3] + red[4] + red[5] + red[6] + red[7];
  float rinv = rsqrtf(tot * (1.0f / D_MODEL) + 1e-6f);

  if (t < sl) {
    for (int p = tid; p < N_HEADS * C_HALF; p += 256) {
      int head = p >> 6;
      int jj = p & 63;
      int i0 = head * D_HEAD + 2 * jj;
      float y0 = row[i0] * rinv * g[i0];
      float y1 = row[i0 + 1] * rinv * g[i0 + 1];
      float cv = cs[jj], sv = sn[jj];
      row[i0] = y0 * cv - y1 * sv;
      row[i0 + 1] = y0 * sv + y1 * cv;
    }
  } else {
    for (int i = tid; i < D_MODEL; i += 256) row[i] = row[i] * rinv * g[i];
  }
}

// ---------------- TF32 flash attention ----------------
// grid (L/128, N_HEADS), 256 threads (8 warps). Q tile 128, KV tile 64.
// Warp w owns S/O rows 16w..16w+15. Softmax fully in registers.
// K/V tiles register-prefetched one iteration ahead.
#define QS_STR 132
#define PS_STR 68
#define ATTN_SMEM (((128 + 64 + 64) * QS_STR + 128 * PS_STR) * 4)

__global__ __launch_bounds__(256) void attn_tf32(
    const float* __restrict__ q, const float* __restrict__ k,
    const float* __restrict__ v, const int* __restrict__ seq_lens,
    float* __restrict__ o) {
  extern __shared__ unsigned sm[];
  unsigned* Qs = sm;                  // [128][132]
  unsigned* Ks = Qs + 128 * QS_STR;   // [64][132]
  unsigned* Vs = Ks + 64 * QS_STR;    // [64][132]
  unsigned* Ps = Vs + 64 * QS_STR;    // [128][68]

  const int tid = threadIdx.x, lane = tid & 31, warp = tid >> 5;
  const int q0 = blockIdx.x << 7, head = blockIdx.y;
  const int seqlen = seq_lens[0];
  const float4* q4 = (const float4*)q;
  const float4* k4 = (const float4*)k;
  const float4* v4 = (const float4*)v;
  const int rs4 = D_MODEL / 4;        // 384
  const int h4 = head * (D_HEAD / 4); // head*32
  const float scq = 0.08838834764831845f;  // 1/sqrt(128)
  const int rq = (lane >> 2);
  const int r_own = (warp << 4) + rq;      // this thread's row (and +8)
  const int ldr = tid >> 5, ldc = tid & 31;  // loader row/col4

  // load + scale + cvt Q tile
#pragma unroll
  for (int i = 0; i < 16; i++) {
    int r = ldr + (i << 3);
    float4 t = q4[(size_t)(q0 + r) * rs4 + h4 + ldc];
    uint4 u = {f2tf(t.x * scq), f2tf(t.y * scq), f2tf(t.z * scq),
               f2tf(t.w * scq)};
    *(uint4*)&Qs[r * QS_STR + (ldc << 2)] = u;
  }

  // prefetch first KV tile into registers
  float4 kr[8], vr[8];
#pragma unroll
  for (int i = 0; i < 8; i++) {
    int r = ldr + (i << 3);
    kr[i] = k4[(size_t)r * rs4 + h4 + ldc];
    vr[i] = v4[(size_t)r * rs4 + h4 + ldc];
  }

  float m0r = -INFINITY, m1r = -INFINITY, l0 = 0.f, l1 = 0.f;
  float oac[16][4];
#pragma unroll
  for (int j = 0; j < 16; j++)
#pragma unroll
    for (int u = 0; u < 4; u++) oac[j][u] = 0.f;

  for (int kt = 0; kt < 64; kt++) {
    __syncthreads();  // prev PV done: Ks/Vs free (and Qs ready on iter 0)
#pragma unroll
    for (int i = 0; i < 8; i++) {
      int r = ldr + (i << 3);
      uint4 uk = {f2tf(kr[i].x), f2tf(kr[i].y), f2tf(kr[i].z), f2tf(kr[i].w)};
      *(uint4*)&Ks[r * QS_STR + (ldc << 2)] = uk;
      uint4 uv = {f2tf(vr[i].x), f2tf(vr[i].y), f2tf(vr[i].z), f2tf(vr[i].w)};
      *(uint4*)&Vs[r * QS_STR + (ldc << 2)] = uv;
    }
    __syncthreads();

    // prefetch next KV tile (latency hidden behind QK+softmax+PV)
    {
      const int ktn = (kt < 63) ? (kt + 1) : kt;
#pragma unroll
      for (int i = 0; i < 8; i++) {
        int r = (ktn << 6) + ldr + (i << 3);
        kr[i] = k4[(size_t)r * rs4 + h4 + ldc];
        vr[i] = v4[(size_t)r * rs4 + h4 + ldc];
      }
    }

    // S = Q K^T : warp rows 16w..16w+15, all 64 cols, k=128
    float sacc[8][4];
#pragma unroll
    for (int j = 0; j < 8; j++)
#pragma unroll
      for (int u = 0; u < 4; u++) sacc[j][u] = 0.f;

#pragma unroll
    for (int s = 0; s < 16; s++) {
      int kk = (s << 3) + (lane & 3);
      unsigned a[4];
      a[0] = Qs[r_own * QS_STR + kk];
      a[1] = Qs[(r_own + 8) * QS_STR + kk];
      a[2] = Qs[r_own * QS_STR + kk + 4];
      a[3] = Qs[(r_own + 8) * QS_STR + kk + 4];
#pragma unroll
      for (int j = 0; j < 8; j++) {
        int n = (j << 3) + rq;
        unsigned b[2] = {Ks[n * QS_STR + kk], Ks[n * QS_STR + kk + 4]};
        mma8(sacc[j], a, b);
      }
    }

    // mask (only triggers on the ragged tail)
    if (((kt << 6) + 63) >= seqlen) {
#pragma unroll
      for (int j = 0; j < 8; j++) {
        int c = (kt << 6) + (j << 3) + ((lane & 3) << 1);
        if (c >= seqlen) { sacc[j][0] = -1e30f; sacc[j][2] = -1e30f; }
        if (c + 1 >= seqlen) { sacc[j][1] = -1e30f; sacc[j][3] = -1e30f; }
      }
    }

    // register softmax: rows r_own (c0,c1) and r_own+8 (c2,c3)
    float mx0 = -INFINITY, mx1 = -INFINITY;
#pragma unroll
    for (int j = 0; j < 8; j++) {
      mx0 = fmaxf(mx0, fmaxf(sacc[j][0], sacc[j][1]));
      mx1 = fmaxf(mx1, fmaxf(sacc[j][2], sacc[j][3]));
    }
    mx0 = fmaxf(mx0, __shfl_xor_sync(0xffffffffu, mx0, 1));
    mx0 = fmaxf(mx0, __shfl_xor_sync(0xffffffffu, mx0, 2));
    mx1 = fmaxf(mx1, __shfl_xor_sync(0xffffffffu, mx1, 1));
    mx1 = fmaxf(mx1, __shfl_xor_sync(0xffffffffu, mx1, 2));
    float mn0 = fmaxf(m0r, mx0), mn1 = fmaxf(m1r, mx1);
    float co0 = __expf(m0r - mn0), co1 = __expf(m1r - mn1);
    float s0 = 0.f, s1 = 0.f;
#pragma unroll
    for (int j = 0; j < 8; j++) {
      float p0 = __expf(sacc[j][0] - mn0);
      float p1 = __expf(sacc[j][1] - mn0);
      float p2 = __expf(sacc[j][2] - mn1);
      float p3 = __expf(sacc[j][3] - mn1);
      s0 += p0 + p1;
      s1 += p2 + p3;
      int c = (j << 3) + ((lane & 3) << 1);
      uint2 w0 = {f2tf(p0), f2tf(p1)};
      *(uint2*)&Ps[r_own * PS_STR + c] = w0;
      uint2 w1 = {f2tf(p2), f2tf(p3)};
      *(uint2*)&Ps[(r_own + 8) * PS_STR + c] = w1;
    }
    s0 += __shfl_xor_sync(0xffffffffu, s0, 1);
    s0 += __shfl_xor_sync(0xffffffffu, s0, 2);
    s1 += __shfl_xor_sync(0xffffffffu, s1, 1);
    s1 += __shfl_xor_sync(0xffffffffu, s1, 2);
    l0 = l0 * co0 + s0;
    l1 = l1 * co1 + s1;
    m0r = mn0;
    m1r = mn1;
#pragma unroll
    for (int j = 0; j < 16; j++) {
      oac[j][0] *= co0;
      oac[j][1] *= co0;
      oac[j][2] *= co1;
      oac[j][3] *= co1;
    }
    __syncwarp();  // Ps rows are per-warp private; warp-level visibility only

    // O += P V : warp rows 16w.., n=128, k=64
#pragma unroll
    for (int s = 0; s < 8; s++) {
      int kk = (s << 3) + (lane & 3);
      unsigned a[4];
      a[0] = Ps[r_own * PS_STR + kk];
      a[1] = Ps[(r_own + 8) * PS_STR + kk];
      a[2] = Ps[r_own * PS_STR + kk + 4];
      a[3] = Ps[(r_own + 8) * PS_STR + kk + 4];
#pragma unroll
      for (int j = 0; j < 16; j++) {
        int n = (j << 3) + rq;
        unsigned b[2] = {Vs[kk * QS_STR + n], Vs[(kk + 4) * QS_STR + n]};
        mma8(oac[j], a, b);
      }
    }
  }

  float i0 = 1.f / l0, i1 = 1.f / l1;
#pragma unroll
  for (int j = 0; j < 16; j++) {
    int c = (j << 3) + ((lane & 3) << 1);
    float2 a = {oac[j][0] * i0, oac[j][1] * i0};
    *(float2*)&o[(size_t)(q0 + r_own) * D_MODEL + head * D_HEAD + c] = a;
    float2 b = {oac[j][2] * i1, oac[j][3] * i1};
    *(float2*)&o[(size_t)(q0 + r_own + 8) * D_MODEL + head * D_HEAD + c] = b;
  }
}

// ---------------- launch ----------------
extern "C" void kernel_launch(void* const* d_in, const int* in_sizes, int n_in,
                              void* d_out, int out_size) {
  const float* x = (const float*)d_in[0];
  const int* seq_lens = (const int*)d_in[1];
  const int* grid_sizes = (const int*)d_in[2];
  const float* fcos = (const float*)d_in[3];
  const float* fsin = (const float*)d_in[4];
  const float* Wq = (const float*)d_in[5];
  const float* bq = (const float*)d_in[6];
  const float* Wk = (const float*)d_in[7];
  const float* bk = (const float*)d_in[8];
  const float* Wv = (const float*)d_in[9];
  const float* bv = (const float*)d_in[10];
  const float* Wo = (const float*)d_in[11];
  const float* bo = (const float*)d_in[12];
  const float* gq = (const float*)d_in[13];
  const float* gk = (const float*)d_in[14];
  float* out = (float*)d_out;

  void *pq, *pk, *pv, *pao;
  cudaGetSymbolAddress(&pq, g_q);
  cudaGetSymbolAddress(&pk, g_k);
  cudaGetSymbolAddress(&pv, g_v);
  cudaGetSymbolAddress(&pao, g_ao);
  float* fq = (float*)pq;
  float* fk = (float*)pk;
  float* fv = (float*)pv;
  float* fao = (float*)pao;

  // fused QKV projection (z selects weights/output)
  dim3 gqkv(D_MODEL / 128, L_SEQ / 128, 3);
  gemm_tf32<<<gqkv, 256>>>(x, Wq, Wk, Wv, bq, bk, bv, fq, fk, fv,
                           L_SEQ, D_MODEL, D_MODEL);

  rmsnorm_rope<<<dim3(L_SEQ, 2), 256>>>(fq, fk, gq, gk, grid_sizes, fcos,
                                        fsin);

  cudaFuncSetAttribute(attn_tf32, cudaFuncAttributeMaxDynamicSharedMemorySize,
                       ATTN_SMEM);
  attn_tf32<<<dim3(L_SEQ / 128, N_HEADS), 256, ATTN_SMEM>>>(fq, fk, fv,
                                                            seq_lens, fao);

  dim3 go(D_MODEL / 128, L_SEQ / 128, 1);
  gemm_tf32<<<go, 256>>>(fao, Wo, Wo, Wo, bo, bo, bo, out, out, out,
                         L_SEQ, D_MODEL, D_MODEL);
}